// round 16
// baseline (speedup 1.0000x reference)
#include <cuda_runtime.h>
#include <cuda_fp16.h>
#include <cstdint>

#define NB 512
#define ND 512
#define NC 200000
#define NYT 1563            // number of 128-row class tiles
#define WAVE_Y 74           // y-tiles per wave (296 CTAs / 4 x-tiles)

static constexpr float cCOS_M  =  0.87758256189037271f;
static constexpr float cSIN_M  =  0.47942553860420301f;
static constexpr float cTHRESH = -0.87758256189037271f;
static constexpr float cMM     =  0.23971276930210150f;
static constexpr float cS      =  64.0f;
static constexpr float cEPS    =  1e-12f;

// Scratch (device globals)
__device__ __align__(1024) __half g_wh[NC * ND];   // weight, fp16 (UNNORMALIZED, in-flight)
__device__ __align__(1024) __half g_fh[NB * ND];   // normalized feats, fp16
__device__ float g_invw[NC];                       // 1/max(||w_c||,eps), in-flight
__device__ float g_tl[NB];
__device__ float g_cosm[NB];
__device__ float g_final[NB];
__device__ float g_tnew;
__device__ int   g_flag[NYT];                      // per-y-tile arrival count (ready at 4)

// ---------------------------------------------------------------------------
// helpers
// ---------------------------------------------------------------------------
__device__ __forceinline__ uint32_t smem_u32(const void* p) {
    uint32_t a;
    asm("{ .reg .u64 t; cvta.to.shared.u64 t, %1; cvt.u32.u64 %0, t; }" : "=r"(a) : "l"(p));
    return a;
}
#define CP_ASYNC16(dst, src) \
    asm volatile("cp.async.cg.shared.global [%0], [%1], 16;" :: "r"(dst), "l"(src) : "memory")
#define CP_COMMIT() asm volatile("cp.async.commit_group;" ::: "memory")
#define CP_WAIT0()  asm volatile("cp.async.wait_group 0;" ::: "memory")

__device__ __forceinline__ void mma_f16(float (&c)[4], const uint32_t (&a)[4],
                                        const uint32_t (&b)[2]) {
    asm volatile(
        "mma.sync.aligned.m16n8k16.row.col.f32.f16.f16.f32 "
        "{%0,%1,%2,%3}, {%4,%5,%6,%7}, {%8,%9}, {%0,%1,%2,%3};\n"
        : "+f"(c[0]), "+f"(c[1]), "+f"(c[2]), "+f"(c[3])
        : "r"(a[0]), "r"(a[1]), "r"(a[2]), "r"(a[3]), "r"(b[0]), "r"(b[1]));
}
#define LDMX4(r0, r1, r2, r3, addr)                                           \
    asm volatile("ldmatrix.sync.aligned.m8n8.x4.shared.b16 {%0,%1,%2,%3}, [%4];" \
                 : "=r"(r0), "=r"(r1), "=r"(r2), "=r"(r3) : "r"(addr))
#define LDMX2(r0, r1, addr)                                                   \
    asm volatile("ldmatrix.sync.aligned.m8n8.x2.shared.b16 {%0,%1}, [%2];"    \
                 : "=r"(r0), "=r"(r1) : "r"(addr))

__device__ __forceinline__ int ld_acquire(const int* p) {
    int v;
    asm volatile("ld.global.acquire.gpu.b32 %0, [%1];" : "=r"(v) : "l"(p) : "memory");
    return v;
}

// ---------------------------------------------------------------------------
// Kernel 1: fused feat-normalize (fp16 A operand) + exact fp32 target logit
// ---------------------------------------------------------------------------
__global__ void k_front(const float* __restrict__ feats, const float* __restrict__ w,
                        const int* __restrict__ labels) {
    int b = blockIdx.x;
    int tid = threadIdx.x;
    const float* x = feats + (size_t)b * ND;
    float f[4];
    float s = 0.f;
#pragma unroll
    for (int j = 0; j < 4; j++) {
        f[j] = x[tid + 128 * j];
        s += f[j] * f[j];
    }
    for (int o = 16; o; o >>= 1) s += __shfl_xor_sync(0xffffffffu, s, o);
    __shared__ float red[4];
    __shared__ float sinv;
    if ((tid & 31) == 0) red[tid >> 5] = s;
    __syncthreads();
    if (tid == 0) sinv = 1.0f / fmaxf(sqrtf(red[0] + red[1] + red[2] + red[3]), cEPS);
    __syncthreads();
    float inv = sinv;
    int lab = labels[b];
    const float* wr = w + (size_t)lab * ND;
    float dot = 0.f, wq = 0.f;
#pragma unroll
    for (int j = 0; j < 4; j++) {
        float fn = f[j] * inv;
        g_fh[(size_t)b * ND + tid + 128 * j] = __float2half_rn(fn);
        float wv = wr[tid + 128 * j];
        dot += fn * wv;
        wq += wv * wv;
    }
    for (int o = 16; o; o >>= 1) {
        dot += __shfl_xor_sync(0xffffffffu, dot, o);
        wq += __shfl_xor_sync(0xffffffffu, wq, o);
    }
    __shared__ float rd[4], rq[4];
    if ((tid & 31) == 0) { rd[tid >> 5] = dot; rq[tid >> 5] = wq; }
    __syncthreads();
    if (tid == 0) {
        float d = rd[0] + rd[1] + rd[2] + rd[3];
        float q = rq[0] + rq[1] + rq[2] + rq[3];
        float tl = d / fmaxf(sqrtf(q), cEPS);
        g_tl[b] = fminf(fmaxf(tl, -1.0f), 1.0f);
    }
}

// ---------------------------------------------------------------------------
// Kernel 2: t_new, cos_theta_m, final  + zero the ready-flags for this launch
// ---------------------------------------------------------------------------
__global__ void k_scalars(const float* __restrict__ t) {
    int b = threadIdx.x;
    for (int i = b; i < NYT; i += 512) g_flag[i] = 0;
    float tl = g_tl[b];
    float s = tl;
    for (int o = 16; o; o >>= 1) s += __shfl_xor_sync(0xffffffffu, s, o);
    __shared__ float red[16];
    if ((b & 31) == 0) red[b >> 5] = s;
    __syncthreads();
    if (b == 0) {
        float tot = 0.f;
#pragma unroll
        for (int i = 0; i < 16; i++) tot += red[i];
        g_tnew = (tot / (float)NB) * 0.01f + 0.99f * t[0];
    }
    float st = sqrtf(fmaxf(1.0f - tl * tl, 0.0f));
    float cm = tl * cCOS_M - st * cSIN_M;
    g_cosm[b] = cm;
    g_final[b] = (tl > cTHRESH) ? cm : (tl - cMM);
}

// ---------------------------------------------------------------------------
// Convert one 32-row quarter of weight -> fp16 + invw. 16 LDG.128/lane fully
// unrolled (single DRAM round-trip), then cvt + STG.64.
// 8 warps x 4 rows; 8 lanes per row; lane owns float4 idx (lane&7)+8k.
// ---------------------------------------------------------------------------
__device__ __forceinline__ void convert_quarter(const float* __restrict__ w, int t, int q) {
    const int wp = threadIdx.x >> 5;
    const int lane = threadIdx.x & 31;
    const int row = t * 128 + q * 32 + wp * 4 + (lane >> 3);
    const bool ok = row < NC;
    const int cr = min(row, NC - 1);
    const float4* src = reinterpret_cast<const float4*>(w + (size_t)cr * ND) + (lane & 7);
    uint2* dst = reinterpret_cast<uint2*>(g_wh + (size_t)cr * ND) + (lane & 7);
    float4 v[16];
#pragma unroll
    for (int k = 0; k < 16; k++) v[k] = src[k * 8];
    float wq = 0.f;
#pragma unroll
    for (int k = 0; k < 16; k++)
        wq += v[k].x * v[k].x + v[k].y * v[k].y + v[k].z * v[k].z + v[k].w * v[k].w;
    if (ok) {
#pragma unroll
        for (int k = 0; k < 16; k++) {
            __half2 h0 = __floats2half2_rn(v[k].x, v[k].y);
            __half2 h1 = __floats2half2_rn(v[k].z, v[k].w);
            uint2 u;
            u.x = *reinterpret_cast<uint32_t*>(&h0);
            u.y = *reinterpret_cast<uint32_t*>(&h1);
            dst[k * 8] = u;
        }
    }
    wq += __shfl_xor_sync(0xffffffffu, wq, 1);
    wq += __shfl_xor_sync(0xffffffffu, wq, 2);
    wq += __shfl_xor_sync(0xffffffffu, wq, 4);
    if (ok && (lane & 7) == 0) g_invw[row] = 1.0f / fmaxf(sqrtf(wq), cEPS);
    __threadfence();
    __syncthreads();
    if (threadIdx.x == 0) atomicAdd(&g_flag[t], 1);
}

// ---------------------------------------------------------------------------
// Kernel 3: GEMM, BK=64 / 2-stage cp.async ring -> 8 barrier events per tile
// AND 2 CTAs/SM (73.7 KB smem/CTA). cp.async issue placed AFTER the barrier
// so the 2-buffer ring is race-free with a single barrier per kt.
// + balanced pre-loop weight conversion (quarter x of tile y+74).
// ---------------------------------------------------------------------------
#define SPAD_H 72      // halfs per smem row (144B) -> conflict-free ldmatrix
#define STAGES 2
#define BK 64
#define KT (ND / BK)   // 8

#define SMEM_BYTES (STAGES * 128 * SPAD_H * 2 * 2)   // 73728

__global__ __launch_bounds__(256, 2) void k_gemm(const float* __restrict__ w,
                                                 const int* __restrict__ labels,
                                                 float* __restrict__ out) {
    extern __shared__ __align__(128) __half smem[];
    __half (*As)[128][SPAD_H] = reinterpret_cast<__half (*)[128][SPAD_H]>(smem);
    __half (*Bs)[128][SPAD_H] =
        reinterpret_cast<__half (*)[128][SPAD_H]>(smem + STAGES * 128 * SPAD_H);

    const int tid = threadIdx.x;
    const int warp = tid >> 5;
    const int lane = tid & 31;
    const int g = lane >> 2;
    const int tg = lane & 3;
    const int wm = (warp >> 2) * 64;   // 2 warps in m
    const int wn = (warp & 3) * 32;    // 4 warps in n

    const int x = blockIdx.x;
    const int y = blockIdx.y;
    const int bm0 = x * 128;           // m tile (fast dim -> weight L2 reuse)
    const int c0 = y * 128;            // class tile

    // ---- balanced pre-loop conversion (outside the MMA loop; 1 round-trip) ----
    if (y < WAVE_Y) convert_quarter(w, y, x);                // wave 0: self
    if (y + WAVE_Y < NYT) convert_quarter(w, y + WAVE_Y, x); // one wave ahead
    if (tid == 0) {
        while (ld_acquire(&g_flag[y]) < 4) __nanosleep(64);
    }
    __syncthreads();

    // ---- staging: row = tid>>1, 64B span (tid&1)*32 halfs, 4 x 16B chunks ----
    const int r1 = tid >> 1;
    const int coff = (tid & 1) * 32;
    const int rb0 = min(c0 + r1, NC - 1);
    const __half* srcA = g_fh + (size_t)(bm0 + r1) * ND + coff;
    const __half* srcB = g_wh + (size_t)rb0 * ND + coff;

    const int a_row = wm + (lane & 15);
    const int a_col = (lane >> 4) * 8;
    const int b_row = wn + (lane & 7);
    const int b_col = ((lane >> 3) & 1) * 8;

    float acc[4][4][4];
#pragma unroll
    for (int mi = 0; mi < 4; mi++)
#pragma unroll
        for (int ni = 0; ni < 4; ni++)
#pragma unroll
            for (int r = 0; r < 4; r++) acc[mi][ni][r] = 0.f;

    // prologue: stage 0 -> buf 0
#pragma unroll
    for (int c = 0; c < 4; c++) {
        CP_ASYNC16(smem_u32(&As[0][r1][coff + c * 8]), srcA + c * 8);
        CP_ASYNC16(smem_u32(&Bs[0][r1][coff + c * 8]), srcB + c * 8);
    }
    CP_COMMIT();

    for (int kt = 0; kt < KT; kt++) {
        CP_WAIT0();       // stage kt resident (issued last iteration / prologue)
        __syncthreads();  // all warps done reading buf (kt+1)&1 (iter kt-1)

        // issue stage kt+1 into the other buffer (safe after the barrier)
        if (kt + 1 < KT) {
            const int s = (kt + 1) & 1;
            const int ko = (kt + 1) * BK;
#pragma unroll
            for (int c = 0; c < 4; c++) {
                CP_ASYNC16(smem_u32(&As[s][r1][coff + c * 8]), srcA + ko + c * 8);
                CP_ASYNC16(smem_u32(&Bs[s][r1][coff + c * 8]), srcB + ko + c * 8);
            }
        }
        CP_COMMIT();

        const __half (*Asb)[SPAD_H] = As[kt & 1];
        const __half (*Bsb)[SPAD_H] = Bs[kt & 1];

#pragma unroll
        for (int ks = 0; ks < 4; ks++) {
            const int kc = ks * 16;
            uint32_t af[4][4];
            uint32_t bf[4][2];
#pragma unroll
            for (int mi = 0; mi < 4; mi++) {
                uint32_t addr = smem_u32(&Asb[a_row + mi * 16][a_col + kc]);
                LDMX4(af[mi][0], af[mi][1], af[mi][2], af[mi][3], addr);
            }
#pragma unroll
            for (int ni = 0; ni < 4; ni++) {
                uint32_t addr = smem_u32(&Bsb[b_row + ni * 8][b_col + kc]);
                LDMX2(bf[ni][0], bf[ni][1], addr);
            }
#pragma unroll
            for (int mi = 0; mi < 4; mi++)
#pragma unroll
                for (int ni = 0; ni < 4; ni++) mma_f16(acc[mi][ni], af[mi], bf[ni]);
        }
    }
    CP_WAIT0();

    // ---- fused CurricularFace epilogue (acc = fn . w_fp16; scale by invw) ----
    const float tnew = g_tnew;
    int ccol[4];
    float2 iw[4];
#pragma unroll
    for (int ni = 0; ni < 4; ni++) {
        int c = c0 + wn + ni * 8 + 2 * tg;
        ccol[ni] = c;
        int cc = min(c, NC - 2);
        iw[ni] = *reinterpret_cast<const float2*>(&g_invw[cc]);
    }

#pragma unroll
    for (int mi = 0; mi < 4; mi++) {
#pragma unroll
        for (int h = 0; h < 2; h++) {
            int m = bm0 + wm + mi * 16 + g + h * 8;
            int lab = labels[m];
            float cm = g_cosm[m];
            float fi = g_final[m];
            float* orow = out + (size_t)m * NC;
#pragma unroll
            for (int ni = 0; ni < 4; ni++) {
                int c = ccol[ni];
                if (c + 1 < NC) {  // NC even: pair fully in-bounds or fully out
                    float x0 = acc[mi][ni][h * 2 + 0] * iw[ni].x;
                    float x1 = acc[mi][ni][h * 2 + 1] * iw[ni].y;
                    x0 = fminf(fmaxf(x0, -1.0f), 1.0f);
                    x1 = fminf(fmaxf(x1, -1.0f), 1.0f);
                    float v0 = (x0 > cm) ? x0 * (tnew + x0) : x0;
                    float v1 = (x1 > cm) ? x1 * (tnew + x1) : x1;
                    if (lab == c) v0 = fi;
                    if (lab == c + 1) v1 = fi;
                    float2 o;
                    o.x = v0 * cS;
                    o.y = v1 * cS;
                    *reinterpret_cast<float2*>(orow + c) = o;
                }
            }
        }
    }
}

// ---------------------------------------------------------------------------
extern "C" void kernel_launch(void* const* d_in, const int* in_sizes, int n_in,
                              void* d_out, int out_size) {
    const float* feats = (const float*)d_in[0];
    const int* labels = (const int*)d_in[1];
    const float* weight = (const float*)d_in[2];
    const float* t = (const float*)d_in[3];
    float* out = (float*)d_out;

    cudaFuncSetAttribute(k_gemm, cudaFuncAttributeMaxDynamicSharedMemorySize, SMEM_BYTES);

    k_front<<<NB, 128>>>(feats, weight, labels);
    k_scalars<<<1, NB>>>(t);

    dim3 grid(4, NYT);  // x fast -> converter linear ids strictly precede waiters
    k_gemm<<<grid, 256, SMEM_BYTES>>>(weight, labels, out);
}

// round 17
// speedup vs baseline: 1.2647x; 1.2647x over previous
#include <cuda_runtime.h>
#include <cuda_fp16.h>
#include <cstdint>

#define NB 512
#define ND 512
#define NC 200000
#define NYT 1563            // number of 128-row class tiles
#define WAVE_Y 74           // y-tiles per wave (296 CTAs / 4 x-tiles)

static constexpr float cCOS_M  =  0.87758256189037271f;
static constexpr float cSIN_M  =  0.47942553860420301f;
static constexpr float cTHRESH = -0.87758256189037271f;
static constexpr float cMM     =  0.23971276930210150f;
static constexpr float cS      =  64.0f;
static constexpr float cEPS    =  1e-12f;

// Scratch (device globals)
__device__ __align__(1024) __half g_wh[NC * ND];   // weight, fp16 (UNNORMALIZED, in-flight)
__device__ __align__(1024) __half g_fh[NB * ND];   // normalized feats, fp16
__device__ float g_invw[NC];                       // 1/max(||w_c||,eps), in-flight
__device__ float g_tl[NB];
__device__ float g_cosm[NB];
__device__ float g_final[NB];
__device__ float g_tnew;
__device__ int   g_flag[NYT];                      // per-y-tile arrival count (ready at 4)

// ---------------------------------------------------------------------------
// helpers
// ---------------------------------------------------------------------------
__device__ __forceinline__ uint32_t smem_u32(const void* p) {
    uint32_t a;
    asm("{ .reg .u64 t; cvta.to.shared.u64 t, %1; cvt.u32.u64 %0, t; }" : "=r"(a) : "l"(p));
    return a;
}
#define CP_ASYNC16(dst, src) \
    asm volatile("cp.async.cg.shared.global [%0], [%1], 16;" :: "r"(dst), "l"(src) : "memory")
#define CP_COMMIT() asm volatile("cp.async.commit_group;" ::: "memory")
#define CP_WAIT2()  asm volatile("cp.async.wait_group 2;" ::: "memory")
#define CP_WAIT0()  asm volatile("cp.async.wait_group 0;" ::: "memory")

__device__ __forceinline__ void mma_f16(float (&c)[4], const uint32_t (&a)[4],
                                        const uint32_t (&b)[2]) {
    asm volatile(
        "mma.sync.aligned.m16n8k16.row.col.f32.f16.f16.f32 "
        "{%0,%1,%2,%3}, {%4,%5,%6,%7}, {%8,%9}, {%0,%1,%2,%3};\n"
        : "+f"(c[0]), "+f"(c[1]), "+f"(c[2]), "+f"(c[3])
        : "r"(a[0]), "r"(a[1]), "r"(a[2]), "r"(a[3]), "r"(b[0]), "r"(b[1]));
}
#define LDMX4(r0, r1, r2, r3, addr)                                           \
    asm volatile("ldmatrix.sync.aligned.m8n8.x4.shared.b16 {%0,%1,%2,%3}, [%4];" \
                 : "=r"(r0), "=r"(r1), "=r"(r2), "=r"(r3) : "r"(addr))
#define LDMX2(r0, r1, addr)                                                   \
    asm volatile("ldmatrix.sync.aligned.m8n8.x2.shared.b16 {%0,%1}, [%2];"    \
                 : "=r"(r0), "=r"(r1) : "r"(addr))

__device__ __forceinline__ int ld_acquire(const int* p) {
    int v;
    asm volatile("ld.global.acquire.gpu.b32 %0, [%1];" : "=r"(v) : "l"(p) : "memory");
    return v;
}

// ---------------------------------------------------------------------------
// Kernel 1: fused feat-normalize (fp16 A operand) + exact fp32 target logit
// ---------------------------------------------------------------------------
__global__ void k_front(const float* __restrict__ feats, const float* __restrict__ w,
                        const int* __restrict__ labels) {
    int b = blockIdx.x;
    int tid = threadIdx.x;
    const float* x = feats + (size_t)b * ND;
    float f[4];
    float s = 0.f;
#pragma unroll
    for (int j = 0; j < 4; j++) {
        f[j] = x[tid + 128 * j];
        s += f[j] * f[j];
    }
    for (int o = 16; o; o >>= 1) s += __shfl_xor_sync(0xffffffffu, s, o);
    __shared__ float red[4];
    __shared__ float sinv;
    if ((tid & 31) == 0) red[tid >> 5] = s;
    __syncthreads();
    if (tid == 0) sinv = 1.0f / fmaxf(sqrtf(red[0] + red[1] + red[2] + red[3]), cEPS);
    __syncthreads();
    float inv = sinv;
    int lab = labels[b];
    const float* wr = w + (size_t)lab * ND;
    float dot = 0.f, wq = 0.f;
#pragma unroll
    for (int j = 0; j < 4; j++) {
        float fn = f[j] * inv;
        g_fh[(size_t)b * ND + tid + 128 * j] = __float2half_rn(fn);
        float wv = wr[tid + 128 * j];
        dot += fn * wv;
        wq += wv * wv;
    }
    for (int o = 16; o; o >>= 1) {
        dot += __shfl_xor_sync(0xffffffffu, dot, o);
        wq += __shfl_xor_sync(0xffffffffu, wq, o);
    }
    __shared__ float rd[4], rq[4];
    if ((tid & 31) == 0) { rd[tid >> 5] = dot; rq[tid >> 5] = wq; }
    __syncthreads();
    if (tid == 0) {
        float d = rd[0] + rd[1] + rd[2] + rd[3];
        float q = rq[0] + rq[1] + rq[2] + rq[3];
        float tl = d / fmaxf(sqrtf(q), cEPS);
        g_tl[b] = fminf(fmaxf(tl, -1.0f), 1.0f);
    }
}

// ---------------------------------------------------------------------------
// Kernel 2: t_new, cos_theta_m, final  + zero the ready-flags for this launch
// ---------------------------------------------------------------------------
__global__ void k_scalars(const float* __restrict__ t) {
    int b = threadIdx.x;
    for (int i = b; i < NYT; i += 512) g_flag[i] = 0;
    float tl = g_tl[b];
    float s = tl;
    for (int o = 16; o; o >>= 1) s += __shfl_xor_sync(0xffffffffu, s, o);
    __shared__ float red[16];
    if ((b & 31) == 0) red[b >> 5] = s;
    __syncthreads();
    if (b == 0) {
        float tot = 0.f;
#pragma unroll
        for (int i = 0; i < 16; i++) tot += red[i];
        g_tnew = (tot / (float)NB) * 0.01f + 0.99f * t[0];
    }
    float st = sqrtf(fmaxf(1.0f - tl * tl, 0.0f));
    float cm = tl * cCOS_M - st * cSIN_M;
    g_cosm[b] = cm;
    g_final[b] = (tl > cTHRESH) ? cm : (tl - cMM);
}

// ---------------------------------------------------------------------------
// Convert one 32-row quarter of weight -> fp16 + invw. 16 LDG.128/lane fully
// unrolled (single DRAM round-trip), then cvt + STG.64.
// 8 warps x 4 rows; 8 lanes per row; lane owns float4 idx (lane&7)+8k.
// ---------------------------------------------------------------------------
__device__ __forceinline__ void convert_quarter(const float* __restrict__ w, int t, int q) {
    const int wp = threadIdx.x >> 5;
    const int lane = threadIdx.x & 31;
    const int row = t * 128 + q * 32 + wp * 4 + (lane >> 3);
    const bool ok = row < NC;
    const int cr = min(row, NC - 1);
    const float4* src = reinterpret_cast<const float4*>(w + (size_t)cr * ND) + (lane & 7);
    uint2* dst = reinterpret_cast<uint2*>(g_wh + (size_t)cr * ND) + (lane & 7);
    float4 v[16];
#pragma unroll
    for (int k = 0; k < 16; k++) v[k] = src[k * 8];
    float wq = 0.f;
#pragma unroll
    for (int k = 0; k < 16; k++)
        wq += v[k].x * v[k].x + v[k].y * v[k].y + v[k].z * v[k].z + v[k].w * v[k].w;
    if (ok) {
#pragma unroll
        for (int k = 0; k < 16; k++) {
            __half2 h0 = __floats2half2_rn(v[k].x, v[k].y);
            __half2 h1 = __floats2half2_rn(v[k].z, v[k].w);
            uint2 u;
            u.x = *reinterpret_cast<uint32_t*>(&h0);
            u.y = *reinterpret_cast<uint32_t*>(&h1);
            dst[k * 8] = u;
        }
    }
    wq += __shfl_xor_sync(0xffffffffu, wq, 1);
    wq += __shfl_xor_sync(0xffffffffu, wq, 2);
    wq += __shfl_xor_sync(0xffffffffu, wq, 4);
    if (ok && (lane & 7) == 0) g_invw[row] = 1.0f / fmaxf(sqrtf(wq), cEPS);
    __threadfence();
    __syncthreads();
    if (threadIdx.x == 0) atomicAdd(&g_flag[t], 1);
}

// ---------------------------------------------------------------------------
// Kernel 3: R11 GEMM (BK=32 / 3-stage / wait1) with fragment-prefetch reorder:
//   after the barrier: ldmatrix ks0 -> cp.async refill -> ldmatrix ks1 (A) ->
//   MMA ks0 -> ldmatrix ks1 (B) -> MMA ks1.
// + balanced pre-loop weight conversion (quarter x of tile y+74).
// ---------------------------------------------------------------------------
#define SPAD_H 40      // halfs per smem row (80B) -> conflict-free ldmatrix
#define STAGES 3
#define BK 32
#define KT (ND / BK)   // 16

#define SMEM_BYTES (STAGES * 128 * SPAD_H * 2 * 2)   // 61440

__global__ __launch_bounds__(256, 2) void k_gemm(const float* __restrict__ w,
                                                 const int* __restrict__ labels,
                                                 float* __restrict__ out) {
    extern __shared__ __align__(128) __half smem[];
    __half (*As)[128][SPAD_H] = reinterpret_cast<__half (*)[128][SPAD_H]>(smem);
    __half (*Bs)[128][SPAD_H] =
        reinterpret_cast<__half (*)[128][SPAD_H]>(smem + STAGES * 128 * SPAD_H);

    const int tid = threadIdx.x;
    const int warp = tid >> 5;
    const int lane = tid & 31;
    const int g = lane >> 2;
    const int tg = lane & 3;
    const int wm = (warp >> 2) * 64;   // 2 warps in m
    const int wn = (warp & 3) * 32;    // 4 warps in n

    const int x = blockIdx.x;
    const int y = blockIdx.y;
    const int bm0 = x * 128;           // m tile (fast dim -> weight L2 reuse)
    const int c0 = y * 128;            // class tile

    // ---- balanced pre-loop conversion (outside the MMA loop; 1 round-trip) ----
    if (y < WAVE_Y) convert_quarter(w, y, x);                // wave 0: self
    if (y + WAVE_Y < NYT) convert_quarter(w, y + WAVE_Y, x); // one wave ahead
    if (tid == 0) {
        while (ld_acquire(&g_flag[y]) < 4) __nanosleep(64);
    }
    __syncthreads();

    // ---- staging: row pair (tid>>2, +64), 16B chunk (tid&3)*8 halfs ----
    const int r1 = tid >> 2;
    const int coff = (tid & 3) * 8;
    const int rb0 = min(c0 + r1, NC - 1);
    const int rb1 = min(c0 + r1 + 64, NC - 1);
    const __half* srcA0 = g_fh + (size_t)(bm0 + r1) * ND + coff;
    const __half* srcA1 = g_fh + (size_t)(bm0 + r1 + 64) * ND + coff;
    const __half* srcB0 = g_wh + (size_t)rb0 * ND + coff;
    const __half* srcB1 = g_wh + (size_t)rb1 * ND + coff;

    const int a_row = wm + (lane & 15);
    const int a_col = (lane >> 4) * 8;
    const int b_row = wn + (lane & 7);
    const int b_col = ((lane >> 3) & 1) * 8;

    float acc[4][4][4];
#pragma unroll
    for (int mi = 0; mi < 4; mi++)
#pragma unroll
        for (int ni = 0; ni < 4; ni++)
#pragma unroll
            for (int r = 0; r < 4; r++) acc[mi][ni][r] = 0.f;

    // prologue: stages 0..1
#pragma unroll
    for (int s = 0; s < STAGES - 1; s++) {
        CP_ASYNC16(smem_u32(&As[s][r1][coff]), srcA0 + s * BK);
        CP_ASYNC16(smem_u32(&As[s][r1 + 64][coff]), srcA1 + s * BK);
        CP_ASYNC16(smem_u32(&Bs[s][r1][coff]), srcB0 + s * BK);
        CP_ASYNC16(smem_u32(&Bs[s][r1 + 64][coff]), srcB1 + s * BK);
        CP_COMMIT();
    }

    for (int kt = 0; kt < KT; kt++) {
        asm volatile("cp.async.wait_group 1;" ::: "memory");  // stage kt resident
        __syncthreads();

        const int st = kt % STAGES;
        const __half (*Asb)[SPAD_H] = As[st];
        const __half (*Bsb)[SPAD_H] = Bs[st];

        // ---- ldmatrix ks=0 first (LDS latency overlaps cp.async issue) ----
        uint32_t af0[4][4], bf0[4][2];
#pragma unroll
        for (int mi = 0; mi < 4; mi++) {
            uint32_t addr = smem_u32(&Asb[a_row + mi * 16][a_col]);
            LDMX4(af0[mi][0], af0[mi][1], af0[mi][2], af0[mi][3], addr);
        }
#pragma unroll
        for (int ni = 0; ni < 4; ni++) {
            uint32_t addr = smem_u32(&Bsb[b_row + ni * 8][b_col]);
            LDMX2(bf0[ni][0], bf0[ni][1], addr);
        }

        // ---- cp.async refill for stage kt+2 ----
        if (kt + STAGES - 1 < KT) {
            int s = (kt + STAGES - 1) % STAGES;
            const int ko = (kt + STAGES - 1) * BK;
            CP_ASYNC16(smem_u32(&As[s][r1][coff]), srcA0 + ko);
            CP_ASYNC16(smem_u32(&As[s][r1 + 64][coff]), srcA1 + ko);
            CP_ASYNC16(smem_u32(&Bs[s][r1][coff]), srcB0 + ko);
            CP_ASYNC16(smem_u32(&Bs[s][r1 + 64][coff]), srcB1 + ko);
        }
        CP_COMMIT();

        // ---- prefetch ks=1 A-fragments (latency drains under ks0 MMAs) ----
        uint32_t af1[4][4];
#pragma unroll
        for (int mi = 0; mi < 4; mi++) {
            uint32_t addr = smem_u32(&Asb[a_row + mi * 16][a_col + 16]);
            LDMX4(af1[mi][0], af1[mi][1], af1[mi][2], af1[mi][3], addr);
        }

        // ---- MMA ks=0 ----
#pragma unroll
        for (int mi = 0; mi < 4; mi++)
#pragma unroll
            for (int ni = 0; ni < 4; ni++) mma_f16(acc[mi][ni], af0[mi], bf0[ni]);

        // ---- ldmatrix ks=1 B-fragments, then MMA ks=1 ----
        uint32_t bf1[4][2];
#pragma unroll
        for (int ni = 0; ni < 4; ni++) {
            uint32_t addr = smem_u32(&Bsb[b_row + ni * 8][b_col + 16]);
            LDMX2(bf1[ni][0], bf1[ni][1], addr);
        }
#pragma unroll
        for (int mi = 0; mi < 4; mi++)
#pragma unroll
            for (int ni = 0; ni < 4; ni++) mma_f16(acc[mi][ni], af1[mi], bf1[ni]);
    }
    CP_WAIT0();

    // ---- fused CurricularFace epilogue (acc = fn . w_fp16; scale by invw) ----
    const float tnew = g_tnew;
    int ccol[4];
    float2 iw[4];
#pragma unroll
    for (int ni = 0; ni < 4; ni++) {
        int c = c0 + wn + ni * 8 + 2 * tg;
        ccol[ni] = c;
        int cc = min(c, NC - 2);
        iw[ni] = *reinterpret_cast<const float2*>(&g_invw[cc]);
    }

#pragma unroll
    for (int mi = 0; mi < 4; mi++) {
#pragma unroll
        for (int h = 0; h < 2; h++) {
            int m = bm0 + wm + mi * 16 + g + h * 8;
            int lab = labels[m];
            float cm = g_cosm[m];
            float fi = g_final[m];
            float* orow = out + (size_t)m * NC;
#pragma unroll
            for (int ni = 0; ni < 4; ni++) {
                int c = ccol[ni];
                if (c + 1 < NC) {  // NC even: pair fully in-bounds or fully out
                    float x0 = acc[mi][ni][h * 2 + 0] * iw[ni].x;
                    float x1 = acc[mi][ni][h * 2 + 1] * iw[ni].y;
                    x0 = fminf(fmaxf(x0, -1.0f), 1.0f);
                    x1 = fminf(fmaxf(x1, -1.0f), 1.0f);
                    float v0 = (x0 > cm) ? x0 * (tnew + x0) : x0;
                    float v1 = (x1 > cm) ? x1 * (tnew + x1) : x1;
                    if (lab == c) v0 = fi;
                    if (lab == c + 1) v1 = fi;
                    float2 o;
                    o.x = v0 * cS;
                    o.y = v1 * cS;
                    *reinterpret_cast<float2*>(orow + c) = o;
                }
            }
        }
    }
}

// ---------------------------------------------------------------------------
extern "C" void kernel_launch(void* const* d_in, const int* in_sizes, int n_in,
                              void* d_out, int out_size) {
    const float* feats = (const float*)d_in[0];
    const int* labels = (const int*)d_in[1];
    const float* weight = (const float*)d_in[2];
    const float* t = (const float*)d_in[3];
    float* out = (float*)d_out;

    cudaFuncSetAttribute(k_gemm, cudaFuncAttributeMaxDynamicSharedMemorySize, SMEM_BYTES);

    k_front<<<NB, 128>>>(feats, weight, labels);
    k_scalars<<<1, NB>>>(t);

    dim3 grid(4, NYT);  // x fast -> converter linear ids strictly precede waiters
    k_gemm<<<grid, 256, SMEM_BYTES>>>(weight, labels, out);
}